// round 16
// baseline (speedup 1.0000x reference)
#include <cuda_runtime.h>
#include <cuda_fp16.h>
#include <math.h>

#define NSTATES (1 << 22)      // 4,194,304 amplitudes
#define ATHREADS 256           // kernelA: 16 complex per thread (radix-16)
#define BTHREADS 256           // kernelBmid: 32 complex per thread

// Inter-kernel statevector stored as half2 (16 MB), amplitudes UNNORMALIZED
// and WITHOUT the per-stage cos(beta) factors (tangent-factored butterflies);
// the exact scale 2^-22 * cb0^44 * cb1^44 is applied once at the end.
__device__ __half2 g_circ[NSTATES];
__device__ double  g_sum;
__device__ unsigned g_count;   // zero-init; reset by last block each run

__device__ __forceinline__ float2 ldState(int idx) {
    return __half22float2(g_circ[idx]);
}
__device__ __forceinline__ void stState(int idx, float2 v) {
    g_circ[idx] = __float22half2_rn(v);
}

// kernelA swizzle (radix-16, 256-thread patterns) — conflict-free:
//   write a=16t+k : slot = k ^ (t&15)     (distinct per 16-lane phase)
//   read  a=256k+t: slot = (t&15)^(t>>4)  (distinct per 16-lane phase)
__device__ __forceinline__ int phi16(int a) {
    return a ^ ((a >> 4) & 15);
}
// kernelB state swizzle (float2 units): flip bit3 by j-bit5 (addr bit 8).
__device__ __forceinline__ int phiS(int a) {
    return a ^ (((a >> 8) & 1) << 3);
}
// kernelB h-tile swizzle (float units): spread jb across bank octets.
__device__ __forceinline__ int phiH(int a) {
    return a ^ (((a >> 8) & 3) << 3);
}

// Tangent-factored butterfly: a'' = a + i*tb*c ; c'' = c + i*tb*a (4 FMA).
__device__ __forceinline__ void stage16(float2* v, const int d, const float tb) {
    #pragma unroll
    for (int m = 0; m < 16; m++) if (!(m & d)) {
        float ax = v[m].x,     ay = v[m].y;
        float cx = v[m | d].x, cy = v[m | d].y;
        v[m].x     = fmaf(-tb, cy, ax);
        v[m].y     = fmaf( tb, cx, ay);
        v[m | d].x = fmaf(-tb, ay, cx);
        v[m | d].y = fmaf( tb, ax, cy);
    }
}
#define RADIX16(v, TB) { stage16(v,1,TB); stage16(v,2,TB); \
                         stage16(v,4,TB); stage16(v,8,TB); }

__device__ __forceinline__ void stage32(float2* v, const int d, const float tb) {
    #pragma unroll
    for (int m = 0; m < 32; m++) if (!(m & d)) {
        float ax = v[m].x,     ay = v[m].y;
        float cx = v[m | d].x, cy = v[m | d].y;
        v[m].x     = fmaf(-tb, cy, ax);
        v[m].y     = fmaf( tb, cx, ay);
        v[m | d].x = fmaf(-tb, ay, cx);
        v[m | d].y = fmaf( tb, ax, cy);
    }
}
#define RADIX32(v, TB) { stage32(v,1,TB);  stage32(v,2,TB);  \
                         stage32(v,4,TB);  stage32(v,8,TB);  \
                         stage32(v,16,TB); }

// ---------------------------------------------------------------------------
// Kernel A_init: layer-0 phase + 12 stages over the low 12 bits; block = 4096
// contiguous amplitudes, 256 threads x 16 complex. Rounds 4+4+4 with rotl4
// storage relabeling (read 256k+t, write 16t+k, both conflict-free under
// phi16). 32 warps/SM. Synthesizes exp(i*gamma0*h) unnormalized; zeroes g_sum.
// ---------------------------------------------------------------------------
__global__ void __launch_bounds__(ATHREADS, 4)
kernelA_init(const float* __restrict__ h,
             const float* __restrict__ gamma,
             const float* __restrict__ beta)
{
    __shared__ float2 sh[4096];   // 32 KB

    const int t    = threadIdx.x;
    const int base = blockIdx.x << 12;
    const float tb = tanf(beta[0]);
    float2 v[16];

    if (blockIdx.x == 0 && t == 0) g_sum = 0.0;
    {
        const float g0 = gamma[0];
        #pragma unroll
        for (int k = 0; k < 16; k++) {                 // 128B/warp coalesced
            float sp, cp;
            __sincosf(g0 * h[base + k * 256 + t], &sp, &cp);
            v[k] = make_float2(cp, sp);                // unnormalized
        }
    }
    RADIX16(v, tb);                                    // logical bits 8..11

    #pragma unroll
    for (int k = 0; k < 16; k++) sh[phi16(t * 16 + k)] = v[k];
    __syncthreads();
    #pragma unroll
    for (int k = 0; k < 16; k++) v[k] = sh[phi16(k * 256 + t)];
    RADIX16(v, tb);                                    // logical bits 4..7
    __syncthreads();

    #pragma unroll
    for (int k = 0; k < 16; k++) sh[phi16(t * 16 + k)] = v[k];
    __syncthreads();
    #pragma unroll
    for (int k = 0; k < 16; k++) v[k] = sh[phi16(k * 256 + t)];
    RADIX16(v, tb);                                    // logical bits 0..3

    // logical = (t>>4)*256 + (t&15)*16 + k: 16 consecutive half2 = 64B/thread
    const int lbase = base + ((t >> 4) << 8) + ((t & 15) << 4);
    #pragma unroll
    for (int c = 0; c < 4; c++) {
        __half2 p0 = __float22half2_rn(v[4*c    ]);
        __half2 p1 = __float22half2_rn(v[4*c + 1]);
        __half2 p2 = __float22half2_rn(v[4*c + 2]);
        __half2 p3 = __float22half2_rn(v[4*c + 3]);
        uint4 pk = make_uint4(*(unsigned*)&p0, *(unsigned*)&p1,
                              *(unsigned*)&p2, *(unsigned*)&p3);
        *(uint4*)&g_circ[lbase + c * 4] = pk;
    }
}

// ---------------------------------------------------------------------------
// Kernel Bmid (unchanged, verified): all high-bit work of BOTH layers.
// Tile = 8 low columns x 1024 rows j (stride 4096); 256 threads x 32 complex;
// 64 KB state smem (fp32) + 32 KB h tile = 96 KB dynamic, 2 CTAs/SM.
// ---------------------------------------------------------------------------
__global__ void __launch_bounds__(BTHREADS, 2)
kernelBmid(const float* __restrict__ h,
           const float* __restrict__ gamma,
           const float* __restrict__ beta)
{
    extern __shared__ float2 sst[];          // [0,8192) state  (64 KB)
    float* shh = (float*)(sst + 8192);       // 8192 floats h tile (32 KB)

    const int t       = threadIdx.x;
    const int l       = t & 7;
    const int jb      = t >> 3;              // 0..31
    const int lowbase = blockIdx.x << 3;
    const float tb0 = tanf(beta[0]);
    const float tb1 = tanf(beta[1]);
    const float g1  = gamma[1];
    float2 v[32];

    // Coalesced state load: j = k*32 + jb (8 lanes cover a 32B sector).
    #pragma unroll
    for (int k = 0; k < 32; k++)
        v[k] = ldState(((k * 32 + jb) << 12) + lowbase + l);
    // Prefetch h tile (overlaps with butterfly compute below).
    #pragma unroll
    for (int m = 0; m < 32; m++) {
        int i = t + m * 256;
        shh[phiH(i)] = h[((i >> 3) << 12) + lowbase + (i & 7)];
    }

    RADIX32(v, tb0);                                   // layer0: j bits 5..9

    #pragma unroll
    for (int k = 0; k < 32; k++) sst[phiS(k * 256 + t)] = v[k];
    __syncthreads();
    #pragma unroll
    for (int k = 0; k < 32; k++) v[k] = sst[phiS(jb * 256 + k * 8 + l)];
    RADIX32(v, tb0);                                   // layer0: j bits 0..4

    // Layer-1 cost phase; register k = j bits 0..4, so h index = jb*32+k.
    #pragma unroll
    for (int k = 0; k < 32; k++) {
        float hv = shh[phiH(jb * 256 + k * 8 + l)];
        float sp, cp;
        __sincosf(g1 * hv, &sp, &cp);
        v[k] = make_float2(v[k].x * cp - v[k].y * sp,
                           v[k].x * sp + v[k].y * cp);
    }

    RADIX32(v, tb1);                                   // layer1: j bits 0..4
    __syncthreads();                                   // drain round-2 reads
    #pragma unroll
    for (int k = 0; k < 32; k++) sst[phiS(jb * 256 + k * 8 + l)] = v[k];
    __syncthreads();
    #pragma unroll
    for (int k = 0; k < 32; k++) v[k] = sst[phiS(k * 256 + t)];
    RADIX32(v, tb1);                                   // layer1: j bits 5..9

    // Coalesced store, same pattern as the load.
    #pragma unroll
    for (int k = 0; k < 32; k++)
        stState(((k * 32 + jb) << 12) + lowbase + l, v[k]);
}

// ---------------------------------------------------------------------------
// Kernel A_reduce: layer-1 low-12 mixing + fused sum(|c|^2 * hS), scaled by
// 2^-22 * cb0^44 * cb1^44. 256 threads x 16 complex, same radix-16 plan as
// A_init. Last block (completion counter) writes out[0], resets counter.
// ---------------------------------------------------------------------------
__global__ void __launch_bounds__(ATHREADS, 4)
kernelA_reduce(const float* __restrict__ hS,
               const float* __restrict__ beta,
               float* __restrict__ out)
{
    __shared__ float2 sh[4096];     // 32 KB
    __shared__ float  hsh[4096];    // 16 KB
    __shared__ double wsum[ATHREADS / 32];

    const int t    = threadIdx.x;
    const int base = blockIdx.x << 12;
    const float tb = tanf(beta[1]);
    float2 v[16];

    #pragma unroll
    for (int k = 0; k < 16; k++)                       // 128B/warp contiguous
        v[k] = ldState(base + k * 256 + t);
    #pragma unroll
    for (int m = 0; m < 16; m++)                       // prefetch hS tile
        hsh[t + m * 256] = hS[base + t + m * 256];

    RADIX16(v, tb);                                    // logical bits 8..11

    #pragma unroll
    for (int k = 0; k < 16; k++) sh[phi16(t * 16 + k)] = v[k];
    __syncthreads();
    #pragma unroll
    for (int k = 0; k < 16; k++) v[k] = sh[phi16(k * 256 + t)];
    RADIX16(v, tb);                                    // logical bits 4..7
    __syncthreads();

    #pragma unroll
    for (int k = 0; k < 16; k++) sh[phi16(t * 16 + k)] = v[k];
    __syncthreads();
    #pragma unroll
    for (int k = 0; k < 16; k++) v[k] = sh[phi16(k * 256 + t)];
    RADIX16(v, tb);                                    // logical bits 0..3

    // logical = (t>>4)*256 + (t&15)*16 + k; hS from smem as float4.
    const int lofs = ((t >> 4) << 8) + ((t & 15) << 4);
    const float4* hs4 = (const float4*)hsh;
    float a0 = 0.0f, a1 = 0.0f;
    #pragma unroll
    for (int c = 0; c < 4; c++) {
        float4 s = hs4[(lofs >> 2) + c];
        a0 = fmaf(fmaf(v[4*c    ].x, v[4*c    ].x, v[4*c    ].y * v[4*c    ].y), s.x, a0);
        a1 = fmaf(fmaf(v[4*c + 1].x, v[4*c + 1].x, v[4*c + 1].y * v[4*c + 1].y), s.y, a1);
        a0 = fmaf(fmaf(v[4*c + 2].x, v[4*c + 2].x, v[4*c + 2].y * v[4*c + 2].y), s.z, a0);
        a1 = fmaf(fmaf(v[4*c + 3].x, v[4*c + 3].x, v[4*c + 3].y * v[4*c + 3].y), s.w, a1);
    }
    double acc = (double)a0 + (double)a1;
    #pragma unroll
    for (int o = 16; o > 0; o >>= 1)
        acc += __shfl_down_sync(0xffffffffu, acc, o);
    if ((t & 31) == 0) wsum[t >> 5] = acc;
    __syncthreads();
    if (t == 0) {
        double blocksum = 0.0;
        #pragma unroll
        for (int w = 0; w < ATHREADS / 32; w++) blocksum += wsum[w];
        atomicAdd(&g_sum, blocksum);
        __threadfence();
        unsigned done = atomicAdd(&g_count, 1u);
        if (done == gridDim.x - 1) {                   // last block finishes
            double total = atomicAdd(&g_sum, 0.0);     // acquire-read
            double c0 = cos((double)beta[0]);
            double c1 = cos((double)beta[1]);
            double scale = (1.0 / 4194304.0) * pow(c0, 44.0) * pow(c1, 44.0);
            out[0] = (float)(total * scale);
            g_count = 0;                               // reset for next replay
        }
    }
}

extern "C" void kernel_launch(void* const* d_in, const int* in_sizes, int n_in,
                              void* d_out, int out_size)
{
    const float* h     = (const float*)d_in[0];
    const float* hS    = (const float*)d_in[1];
    const float* gamma = (const float*)d_in[2];
    const float* beta  = (const float*)d_in[3];
    float* out = (float*)d_out;

    const int smemB = 8192 * sizeof(float2) + 8192 * sizeof(float); // 96 KB
    cudaFuncSetAttribute((const void*)kernelBmid,
                         cudaFuncAttributeMaxDynamicSharedMemorySize, smemB);

    // Layer 0: init + phase(gamma0) + low-12 mixing (also zeroes g_sum)
    kernelA_init<<<1024, ATHREADS>>>(h, gamma, beta);
    // High-10 mixing of layer 0, phase(gamma1), high-10 mixing of layer 1
    kernelBmid<<<512, BTHREADS, smemB>>>(h, gamma, beta);
    // Layer 1: low-12 mixing + fused reduction + direct out[0] write
    kernelA_reduce<<<1024, ATHREADS>>>(hS, beta, out);
}

// round 17
// speedup vs baseline: 1.1238x; 1.1238x over previous
#include <cuda_runtime.h>
#include <cuda_fp16.h>
#include <math.h>

#define NSTATES (1 << 22)      // 4,194,304 amplitudes
#define ATHREADS 128           // kernelA: 32 complex per thread
#define BTHREADS 256           // kernelBmid: 32 complex per thread

// Inter-kernel statevector stored as half2 (16 MB), amplitudes UNNORMALIZED
// and WITHOUT the per-stage cos(beta) factors (tangent-factored butterflies);
// the exact scale 2^-22 * cb0^44 * cb1^44 is applied once at the end.
__device__ __half2 g_circ[NSTATES];
__device__ double  g_sum;
__device__ unsigned g_count;   // zero-init; reset by last block each run

__device__ __forceinline__ float2 ldState(int idx) {
    return __half22float2(g_circ[idx]);
}
__device__ __forceinline__ void stState(int idx, float2 v) {
    g_circ[idx] = __float22half2_rn(v);
}

// kernelA swizzle (radix-32, 128-thread patterns) — verified conflict-free.
__device__ __forceinline__ int phi(int a) {
    return a ^ ((a >> 5) & 15);
}
// kernelB state swizzle (float2 units): flip bit3 by j-bit5 (addr bit 8).
__device__ __forceinline__ int phiS(int a) {
    return a ^ (((a >> 8) & 1) << 3);
}
// kernelB h-tile swizzle (float units): spread jb across bank octets.
__device__ __forceinline__ int phiH(int a) {
    return a ^ (((a >> 8) & 3) << 3);
}

// Tangent-factored butterfly: a'' = a + i*tb*c ; c'' = c + i*tb*a (4 FMA).
__device__ __forceinline__ void stage32(float2* v, const int d, const float tb) {
    #pragma unroll
    for (int m = 0; m < 32; m++) if (!(m & d)) {
        float ax = v[m].x,     ay = v[m].y;
        float cx = v[m | d].x, cy = v[m | d].y;
        v[m].x     = fmaf(-tb, cy, ax);
        v[m].y     = fmaf( tb, cx, ay);
        v[m | d].x = fmaf(-tb, ay, cx);
        v[m | d].y = fmaf( tb, ax, cy);
    }
}
#define RADIX32(v, TB) { stage32(v,1,TB);  stage32(v,2,TB);  \
                         stage32(v,4,TB);  stage32(v,8,TB);  \
                         stage32(v,16,TB); }

// ---------------------------------------------------------------------------
// Kernel A_init (R15-verified): layer-0 phase + 12 low-bit stages; block =
// 4096 contiguous amplitudes, 128 threads x 32 complex, rounds 5+5+2 (rotl5
// relabeling). Triggers the dependent Bmid launch when entering its final
// round (Bmid's h-prefetch overlaps this kernel's tail).
// ---------------------------------------------------------------------------
__global__ void __launch_bounds__(ATHREADS, 4)
kernelA_init(const float* __restrict__ h,
             const float* __restrict__ gamma,
             const float* __restrict__ beta)
{
    __shared__ float2 sh[4096];   // 32 KB

    const int t    = threadIdx.x;
    const int base = blockIdx.x << 12;
    const float tb = tanf(beta[0]);
    float2 v[32];

    if (blockIdx.x == 0 && t == 0) g_sum = 0.0;
    {
        const float g0 = gamma[0];
        #pragma unroll
        for (int k = 0; k < 32; k++) {
            float sp, cp;
            __sincosf(g0 * h[base + k * 128 + t], &sp, &cp);
            v[k] = make_float2(cp, sp);                // unnormalized
        }
    }
    RADIX32(v, tb);                                    // logical bits 7..11

    #pragma unroll
    for (int k = 0; k < 32; k++) sh[phi(t * 32 + k)] = v[k];
    __syncthreads();
    #pragma unroll
    for (int k = 0; k < 32; k++) v[k] = sh[phi(k * 128 + t)];
    RADIX32(v, tb);                                    // logical bits 2..6
    __syncthreads();

    #pragma unroll
    for (int k = 0; k < 32; k++) sh[phi(t * 32 + k)] = v[k];
    __syncthreads();

    if (t == 0) cudaTriggerProgrammaticLaunchCompletion();

    #pragma unroll
    for (int k = 0; k < 32; k++) v[k] = sh[phi(k * 128 + t)];
    stage32(v, 8,  tb);                                // logical bit 0
    stage32(v, 16, tb);                                // logical bit 1

    // logical = (k&7)*512 + t*4 + (k>>3): 4 half2 = 16B per (c), contiguous
    #pragma unroll
    for (int c = 0; c < 8; c++) {
        __half2 p0 = __float22half2_rn(v[c]);
        __half2 p1 = __float22half2_rn(v[c + 8]);
        __half2 p2 = __float22half2_rn(v[c + 16]);
        __half2 p3 = __float22half2_rn(v[c + 24]);
        uint4 pk = make_uint4(*(unsigned*)&p0, *(unsigned*)&p1,
                              *(unsigned*)&p2, *(unsigned*)&p3);
        *(uint4*)&g_circ[base + c * 512 + t * 4] = pk;
    }
}

// ---------------------------------------------------------------------------
// Kernel Bmid (R15-verified core + PDL): all high-bit work of BOTH layers.
// Tile = 8 low columns x 1024 rows j (stride 4096); 256 threads x 32 complex;
// 64 KB state smem + 32 KB h tile = 96 KB dynamic, 2 CTAs/SM.
// PDL: prefetches the (input-only) h tile BEFORE cudaGridDependencySync, so
// it overlaps A_init's tail; state loads come after the sync.
// ---------------------------------------------------------------------------
__global__ void __launch_bounds__(BTHREADS, 2)
kernelBmid(const float* __restrict__ h,
           const float* __restrict__ gamma,
           const float* __restrict__ beta)
{
    extern __shared__ float2 sst[];          // [0,8192) state  (64 KB)
    float* shh = (float*)(sst + 8192);       // 8192 floats h tile (32 KB)

    const int t       = threadIdx.x;
    const int l       = t & 7;
    const int jb      = t >> 3;              // 0..31
    const int lowbase = blockIdx.x << 3;
    const float tb0 = tanf(beta[0]);
    const float tb1 = tanf(beta[1]);
    const float g1  = gamma[1];
    float2 v[32];

    // Independent-input prefetch (overlaps A_init tail under PDL).
    #pragma unroll
    for (int m = 0; m < 32; m++) {
        int i = t + m * 256;
        shh[phiH(i)] = h[((i >> 3) << 12) + lowbase + (i & 7)];
    }

    cudaGridDependencySynchronize();         // A_init's g_circ now visible

    // Coalesced state load: j = k*32 + jb (8 lanes cover a 32B sector).
    #pragma unroll
    for (int k = 0; k < 32; k++)
        v[k] = ldState(((k * 32 + jb) << 12) + lowbase + l);

    RADIX32(v, tb0);                                   // layer0: j bits 5..9

    #pragma unroll
    for (int k = 0; k < 32; k++) sst[phiS(k * 256 + t)] = v[k];
    __syncthreads();
    #pragma unroll
    for (int k = 0; k < 32; k++) v[k] = sst[phiS(jb * 256 + k * 8 + l)];
    RADIX32(v, tb0);                                   // layer0: j bits 0..4

    // Layer-1 cost phase; register k = j bits 0..4, so h index = jb*32+k.
    #pragma unroll
    for (int k = 0; k < 32; k++) {
        float hv = shh[phiH(jb * 256 + k * 8 + l)];
        float sp, cp;
        __sincosf(g1 * hv, &sp, &cp);
        v[k] = make_float2(v[k].x * cp - v[k].y * sp,
                           v[k].x * sp + v[k].y * cp);
    }

    RADIX32(v, tb1);                                   // layer1: j bits 0..4
    __syncthreads();                                   // drain round-2 reads
    #pragma unroll
    for (int k = 0; k < 32; k++) sst[phiS(jb * 256 + k * 8 + l)] = v[k];
    __syncthreads();

    if (t == 0) cudaTriggerProgrammaticLaunchCompletion();

    #pragma unroll
    for (int k = 0; k < 32; k++) v[k] = sst[phiS(k * 256 + t)];
    RADIX32(v, tb1);                                   // layer1: j bits 5..9

    // Coalesced store, same pattern as the load.
    #pragma unroll
    for (int k = 0; k < 32; k++)
        stState(((k * 32 + jb) << 12) + lowbase + l, v[k]);
}

// ---------------------------------------------------------------------------
// Kernel A_reduce (R15-verified core + PDL): layer-1 low-12 mixing + fused
// sum(|c|^2 * hS) scaled by 2^-22 * cb0^44 * cb1^44. PDL: prefetches the
// (input-only) hS tile before the dependency sync, overlapping Bmid's tail.
// Last block (completion counter) writes out[0], resets counter.
// ---------------------------------------------------------------------------
__global__ void __launch_bounds__(ATHREADS, 4)
kernelA_reduce(const float* __restrict__ hS,
               const float* __restrict__ beta,
               float* __restrict__ out)
{
    __shared__ float2 sh[4096];     // 32 KB
    __shared__ float  hsh[4096];    // 16 KB
    __shared__ double wsum[ATHREADS / 32];

    const int t    = threadIdx.x;
    const int base = blockIdx.x << 12;
    const float tb = tanf(beta[1]);
    float2 v[32];

    // Independent-input prefetch (overlaps Bmid tail under PDL).
    #pragma unroll
    for (int m = 0; m < 32; m++)
        hsh[t + m * 128] = hS[base + t + m * 128];

    cudaGridDependencySynchronize();         // Bmid's g_circ now visible

    #pragma unroll
    for (int k = 0; k < 32; k++)                       // 128B/warp contiguous
        v[k] = ldState(base + k * 128 + t);

    RADIX32(v, tb);                                    // logical bits 7..11

    #pragma unroll
    for (int k = 0; k < 32; k++) sh[phi(t * 32 + k)] = v[k];
    __syncthreads();
    #pragma unroll
    for (int k = 0; k < 32; k++) v[k] = sh[phi(k * 128 + t)];
    RADIX32(v, tb);                                    // logical bits 2..6
    __syncthreads();

    #pragma unroll
    for (int k = 0; k < 32; k++) sh[phi(t * 32 + k)] = v[k];
    __syncthreads();
    #pragma unroll
    for (int k = 0; k < 32; k++) v[k] = sh[phi(k * 128 + t)];
    stage32(v, 8,  tb);                                // logical bit 0
    stage32(v, 16, tb);                                // logical bit 1

    // logical c*512 + t*4 + q -> v[c + 8*q]; hS from smem as float4.
    const float4* hs4 = (const float4*)hsh;
    float a0 = 0.0f, a1 = 0.0f;
    #pragma unroll
    for (int c = 0; c < 8; c++) {
        float4 s = hs4[c * 128 + t];
        a0 = fmaf(fmaf(v[c     ].x, v[c     ].x, v[c     ].y * v[c     ].y), s.x, a0);
        a1 = fmaf(fmaf(v[c +  8].x, v[c +  8].x, v[c +  8].y * v[c +  8].y), s.y, a1);
        a0 = fmaf(fmaf(v[c + 16].x, v[c + 16].x, v[c + 16].y * v[c + 16].y), s.z, a0);
        a1 = fmaf(fmaf(v[c + 24].x, v[c + 24].x, v[c + 24].y * v[c + 24].y), s.w, a1);
    }
    double acc = (double)a0 + (double)a1;
    #pragma unroll
    for (int o = 16; o > 0; o >>= 1)
        acc += __shfl_down_sync(0xffffffffu, acc, o);
    if ((t & 31) == 0) wsum[t >> 5] = acc;
    __syncthreads();
    if (t == 0) {
        atomicAdd(&g_sum, (wsum[0] + wsum[1]) + (wsum[2] + wsum[3]));
        __threadfence();
        unsigned done = atomicAdd(&g_count, 1u);
        if (done == gridDim.x - 1) {                   // last block finishes
            double total = atomicAdd(&g_sum, 0.0);     // acquire-read
            double c0 = cos((double)beta[0]);
            double c1 = cos((double)beta[1]);
            double scale = (1.0 / 4194304.0) * pow(c0, 44.0) * pow(c1, 44.0);
            out[0] = (float)(total * scale);
            g_count = 0;                               // reset for next replay
        }
    }
}

extern "C" void kernel_launch(void* const* d_in, const int* in_sizes, int n_in,
                              void* d_out, int out_size)
{
    const float* h     = (const float*)d_in[0];
    const float* hS    = (const float*)d_in[1];
    const float* gamma = (const float*)d_in[2];
    const float* beta  = (const float*)d_in[3];
    float* out = (float*)d_out;

    const int smemB = 8192 * sizeof(float2) + 8192 * sizeof(float); // 96 KB
    cudaFuncSetAttribute((const void*)kernelBmid,
                         cudaFuncAttributeMaxDynamicSharedMemorySize, smemB);

    // PDL attribute for the two dependent launches.
    cudaLaunchAttribute pdlAttr;
    pdlAttr.id = cudaLaunchAttributeProgrammaticStreamSerialization;
    pdlAttr.val.programmaticStreamSerializationAllowed = 1;

    // Layer 0: init + phase(gamma0) + low-12 mixing (normal launch)
    kernelA_init<<<1024, ATHREADS>>>(h, gamma, beta);

    // High-bit work of both layers — PDL: h prefetch overlaps A_init tail.
    {
        cudaLaunchConfig_t cfg = {};
        cfg.gridDim = dim3(512);
        cfg.blockDim = dim3(BTHREADS);
        cfg.dynamicSmemBytes = smemB;
        cfg.attrs = &pdlAttr;
        cfg.numAttrs = 1;
        cudaLaunchKernelEx(&cfg, kernelBmid, h, gamma, beta);
    }

    // Layer 1 low mixing + reduction — PDL: hS prefetch overlaps Bmid tail.
    {
        cudaLaunchConfig_t cfg = {};
        cfg.gridDim = dim3(1024);
        cfg.blockDim = dim3(ATHREADS);
        cfg.attrs = &pdlAttr;
        cfg.numAttrs = 1;
        cudaLaunchKernelEx(&cfg, kernelA_reduce, hS, beta, out);
    }
}